// round 10
// baseline (speedup 1.0000x reference)
#include <cuda_runtime.h>
#include <cstdint>
#include <math.h>

#define LEVELS 3
#define BINS 9
#define NATOMS 51
#define ADIM 6
#define NB 4096
#define SLAB 8262                 // full per-batch floats (162*51)
#define NUNITS 9
#define TROWS 18                  // rows per unit
#define TSLAB 918                 // floats per unit (18*51)
#define TSLAB_BYTES 3672          // == 8 mod 16
#define LOAD_BYTES 3680           // fixed 16B-multiple bulk-load size
#define V_MIN_C (-10.0f)
#define V_MAX_C (10.0f)
#define DZ_C (0.4f)

#define THREADS 64
#define GRID (NB * NUNITS)        // 36864

// dyn smem (16B-aligned base):
//   [0,16)           mbarrier
//   [16, 16+3680)    input slot  (data at +m)
//   [3696, +3672)    output slot (float-indexed, no alignment games)
#define OFF_MBAR 0
#define OFF_IN   16
#define OFF_OUT  (16 + LOAD_BYTES)          // 3696
#define DYN_BYTES (OFF_OUT + TSLAB_BYTES)   // 7368

__global__ __launch_bounds__(THREADS)
void c2f_kernel(const float* __restrict__ q,
                const float* __restrict__ reward,
                const float* __restrict__ discount,
                const float* __restrict__ act,
                const float* __restrict__ support,
                const float* __restrict__ low0,
                const float* __restrict__ high0,
                float* __restrict__ out)
{
    const int T = blockIdx.x;             // unit index
    const int t = threadIdx.x;
    const int b = T / NUNITS;             // batch element
    const int unit = T - b * NUNITS;
    const int m = (T & 1) * 8;            // byte misalignment of T*3672 mod 16

    extern __shared__ __align__(16) char dyn[];
    const uint32_t smem_base = (uint32_t)__cvta_generic_to_shared(dyn);
    const uint32_t mbar = smem_base + OFF_MBAR;

    float* sp = reinterpret_cast<float*>(dyn + OFF_IN + m);   // staged probs
    float* so = reinterpret_cast<float*>(dyn + OFF_OUT);      // staged result

    __shared__ __align__(16) float4 stbl[NATOMS];   // (wl, wu, lower_bits, 0)

    // ---- t0: init mbar, fire TMA immediately (tables overlap the flight) ----
    if (t == 0) {
        asm volatile("mbarrier.init.shared.b64 [%0], 1;" :: "r"(mbar) : "memory");
        const char* src = reinterpret_cast<const char*>(q) + (size_t)T * TSLAB_BYTES - m;
        asm volatile("mbarrier.arrive.expect_tx.shared.b64 _, [%0], %1;"
                     :: "r"(mbar), "r"((uint32_t)LOAD_BYTES) : "memory");
        asm volatile("cp.async.bulk.shared::cta.global.mbarrier::complete_tx::bytes "
                     "[%0], [%1], %2, [%3];"
                     :: "r"(smem_base + OFF_IN), "l"(src),
                        "r"((uint32_t)LOAD_BYTES), "r"(mbar) : "memory");
    }

    // ---- projection table (block-uniform; depends only on b) ----
    if (t < NATOMS) {
        const float r = reward[b];
        const float d = discount[b];
        const float z = support[t];
        float Tz = fminf(fmaxf(r + d * z, V_MIN_C), V_MAX_C);
        float bc = (Tz - V_MIN_C) / DZ_C;
        int lo = (int)floorf(bc);
        int up = (int)ceilf(bc);
        if (up > 0 && lo == up) lo -= 1;              // reference fixup 1
        if (lo < NATOMS - 1 && lo == up) up += 1;     // reference fixup 2 => up==lo+1
        stbl[t] = make_float4((float)up - bc, bc - (float)lo,
                              __int_as_float(lo), 0.0f);
    }

    // ---- encode + decode: only in the unit==0 CTA of each batch element ----
    if (unit == 0 && t >= 52 && t < 52 + ADIM) {
        const int dim = t - 52;
        const float a = act[b * ADIM + dim];
        float low = low0[dim], high = high0[dim];
        float idx[LEVELS];
        #pragma unroll
        for (int lvl = 0; lvl < LEVELS; lvl++) {
            float sr = (high - low) / (float)BINS;
            float id = floorf((a - low) / sr);
            id = fminf(fmaxf(id, 0.0f), (float)(BINS - 1));
            float na = fminf(fmaxf(low + sr * id, -1.0f), 1.0f);
            low  = fmaxf(-1.0f, na);
            high = fminf(1.0f, na + sr);
            idx[lvl] = id;
        }
        low = low0[dim]; high = high0[dim];
        #pragma unroll
        for (int lvl = 0; lvl < LEVELS; lvl++) {
            float sr = (high - low) / (float)BINS;
            float cont = low + sr * idx[lvl];
            low  = fmaxf(-1.0f, cont);
            high = fminf(1.0f, cont + sr);
        }
        out[(size_t)NB * SLAB + (size_t)b * ADIM + dim] = 0.5f * (high + low);
    }

    __syncthreads();   // mbar init + table visible to all

    // ---- wait for the slab ----
    asm volatile(
        "{\n\t"
        ".reg .pred P;\n\t"
        "WAIT_%=:\n\t"
        "mbarrier.try_wait.parity.acquire.cta.shared::cta.b64 P, [%0], 0, 0x989680;\n\t"
        "@!P bra WAIT_%=;\n\t"
        "}"
        :: "r"(mbar) : "memory");

    // ---- walk: one thread per row, single pass j=0..50, gap zero-fill ----
    if (t < TROWS) {
        const float* pr = sp + t * NATOMS;   // stride 51 (odd) -> conflict-free
        float* po = so + t * NATOMS;
        int kcur = __float_as_int(stbl[0].z);
        for (int k = 0; k < kcur; k++) po[k] = 0.0f;
        float accA = 0.0f, accB = 0.0f, carryB = 0.0f;
        #pragma unroll 1
        for (int j = 0; j < NATOMS; j++) {
            const float4 tb = stbl[j];       // LDS.128 broadcast
            const int kj = __float_as_int(tb.z);
            if (kj != kcur) {                // uniform branch
                po[kcur] = accA + carryB;
                if (kj == kcur + 1) {
                    carryB = accB;
                } else {
                    po[kcur + 1] = accB;
                    for (int k = kcur + 2; k < kj; k++) po[k] = 0.0f;
                    carryB = 0.0f;
                }
                accA = 0.0f; accB = 0.0f; kcur = kj;
            }
            const float p = pr[j];
            accA = fmaf(p, tb.x, accA);
            accB = fmaf(p, tb.y, accB);
        }
        po[kcur] = accA + carryB;
        po[kcur + 1] = accB;                 // kcur <= 49 -> safe
        for (int k = kcur + 2; k < NATOMS; k++) po[k] = 0.0f;
    }
    __syncthreads();

    // ---- copy-out: plain coalesced STG, no drain needed before exit ----
    {
        float* dst = out + (size_t)T * TSLAB;
        #pragma unroll 4
        for (int i = t; i < TSLAB; i += THREADS) dst[i] = so[i];
    }
}

extern "C" void kernel_launch(void* const* d_in, const int* in_sizes, int n_in,
                              void* d_out, int out_size)
{
    const float* q        = (const float*)d_in[0];
    const float* reward   = (const float*)d_in[1];
    const float* discount = (const float*)d_in[2];
    const float* act      = (const float*)d_in[3];
    const float* support  = (const float*)d_in[4];
    const float* low0     = (const float*)d_in[5];
    const float* high0    = (const float*)d_in[6];
    float* out = (float*)d_out;

    cudaFuncSetAttribute(c2f_kernel, cudaFuncAttributeMaxDynamicSharedMemorySize,
                         DYN_BYTES);
    c2f_kernel<<<GRID, THREADS, DYN_BYTES>>>(q, reward, discount, act, support,
                                             low0, high0, out);
}